// round 1
// baseline (speedup 1.0000x reference)
#include <cuda_runtime.h>
#include <cstdint>

// Problem constants
#define BATCH   128
#define SEQT    2048
#define EMB     128
#define HID     256
#define G4      1024   // 4*HID
#define VOCABN  128
#define OUTN    2

// Parallel decomposition
#define CLUSTER   8      // CTAs per cluster
#define BG        8      // batch elements per cluster
#define USLICE    32     // hidden units per CTA (HID / CLUSTER)
#define NCOL      128    // USLICE * 4 gates
#define NTHREADS  256

// table[v][g*256 + j] = emb[v] @ W_ih[g*256+j]^T + b_ih + b_hh
__device__ float d_table[VOCABN * G4];

__global__ void build_table_kernel(const float* __restrict__ emb,
                                   const float* __restrict__ W_ih,
                                   const float* __restrict__ b_ih,
                                   const float* __restrict__ b_hh) {
    __shared__ float se[EMB];
    int v = blockIdx.x;
    int tid = threadIdx.x;
    if (tid < EMB) se[tid] = emb[v * EMB + tid];
    __syncthreads();
    for (int j = tid; j < G4; j += blockDim.x) {
        float acc = b_ih[j] + b_hh[j];
        const float* w = W_ih + (size_t)j * EMB;
        #pragma unroll 8
        for (int e = 0; e < EMB; e++) acc += se[e] * w[e];
        d_table[v * G4 + j] = acc;
    }
}

__device__ __forceinline__ uint32_t smem_u32(const void* p) {
    uint32_t a;
    asm("{ .reg .u64 t; cvta.to.shared.u64 t, %1; cvt.u32.u64 %0, t; }"
        : "=r"(a) : "l"(p));
    return a;
}

__device__ __forceinline__ void st_shared_cluster_f32(uint32_t addr, uint32_t rank, float v) {
    asm volatile(
        "{\n\t.reg .b32 r;\n\t"
        "mapa.shared::cluster.u32 r, %0, %1;\n\t"
        "st.shared::cluster.f32 [r], %2;\n\t}"
        :: "r"(addr), "r"(rank), "f"(v) : "memory");
}

__device__ __forceinline__ void cluster_sync_ptx() {
    asm volatile("barrier.cluster.arrive.aligned;" ::: "memory");
    asm volatile("barrier.cluster.wait.aligned;" ::: "memory");
}

__device__ __forceinline__ float sigf(float x) {
    return 1.0f / (1.0f + __expf(-x));
}
__device__ __forceinline__ float tanhf_fast(float x) {
    // tanh(x) = 1 - 2/(exp(2x)+1); saturates correctly for |x| large
    return 1.0f - 2.0f / (__expf(2.0f * x) + 1.0f);
}

// Dynamic SMEM layout (floats):
//   Wsl [256][128]       : W_hh slice, k-major, col = u*4 + gate      (32768)
//   hb  [2][256][8]      : double-buffered full hidden state [k][b]   ( 4096)
//   gbuf[8][128]         : per-step gate preactivations [b][col]      ( 1024)
#define WSL_F   (HID * NCOL)
#define HB_F    (2 * HID * BG)
#define GBUF_F  (BG * NCOL)
#define SMEM_F  (WSL_F + HB_F + GBUF_F)
#define SMEM_BYTES (SMEM_F * 4)

__global__ void __cluster_dims__(CLUSTER, 1, 1) __launch_bounds__(NTHREADS, 1)
lstm_persistent_kernel(const int* __restrict__ x,
                       const float* __restrict__ W_hh,
                       const float* __restrict__ fc_W,
                       const float* __restrict__ fc_b,
                       float* __restrict__ out) {
    extern __shared__ float smem[];
    float* Wsl  = smem;                 // [k][col]
    float* hb   = smem + WSL_F;         // [buf][k][b]
    float* gbuf = hb + HB_F;            // [b][col]

    const int tid = threadIdx.x;
    uint32_t rank;
    asm("mov.u32 %0, %%cluster_ctarank;" : "=r"(rank));
    const int batch_base = (blockIdx.x / CLUSTER) * BG;

    // --- Load W_hh slice: Wsl[k][col] = W_hh[(g*256 + rank*32 + u) * 256 + k]
    for (int idx = tid; idx < WSL_F; idx += NTHREADS) {
        int k = idx >> 7;
        int col = idx & 127;
        int u = col >> 2;
        int g = col & 3;
        int row = g * HID + (int)rank * USLICE + u;
        Wsl[idx] = W_hh[row * HID + k];
    }
    // --- Zero both hidden buffers
    for (int idx = tid; idx < HB_F; idx += NTHREADS) hb[idx] = 0.0f;
    __syncthreads();
    cluster_sync_ptx();  // all CTAs zeroed before any peer writes

    // GEMM role: this thread computes gate col for 4 batch elems
    const int col = tid & 127;
    const int bh  = tid >> 7;            // batch half: b in [bh*4, bh*4+4)
    const int u_c = col >> 2;
    const int g_c = col & 3;
    const int grow = g_c * HID + (int)rank * USLICE + u_c;  // global gate row

    // Gating role: this thread owns cell (bb, uu); c state lives in a register
    const int bb = tid >> 5;             // warp == batch element
    const int uu = tid & 31;
    float c_reg = 0.0f;

    const uint32_t hb_addr = smem_u32(hb);
    const int b0 = batch_base + bh * 4;
    const int* xr0 = x + (size_t)(b0 + 0) * SEQT;
    const int* xr1 = x + (size_t)(b0 + 1) * SEQT;
    const int* xr2 = x + (size_t)(b0 + 2) * SEQT;
    const int* xr3 = x + (size_t)(b0 + 3) * SEQT;
    const float* tabc = d_table + grow;
    const float* wp = Wsl + col;

    for (int t = 0; t < SEQT; t++) {
        const int p = t & 1;

        // xg gather (issue early; overlaps with GEMM)
        int v0 = xr0[t], v1 = xr1[t], v2 = xr2[t], v3 = xr3[t];
        float acc0 = tabc[v0 * G4];
        float acc1 = tabc[v1 * G4];
        float acc2 = tabc[v2 * G4];
        float acc3 = tabc[v3 * G4];

        // GEMM: acc[b] += sum_k W[grow][k] * h[k][b]
        const float4* hp = reinterpret_cast<const float4*>(hb + p * (HID * BG)) + bh;
        #pragma unroll 16
        for (int k = 0; k < HID; k++) {
            float w = wp[k * NCOL];
            float4 hv = hp[k * 2];
            acc0 = fmaf(w, hv.x, acc0);
            acc1 = fmaf(w, hv.y, acc1);
            acc2 = fmaf(w, hv.z, acc2);
            acc3 = fmaf(w, hv.w, acc3);
        }

        // stage preactivations for regrouping
        gbuf[(bh * 4 + 0) * NCOL + col] = acc0;
        gbuf[(bh * 4 + 1) * NCOL + col] = acc1;
        gbuf[(bh * 4 + 2) * NCOL + col] = acc2;
        gbuf[(bh * 4 + 3) * NCOL + col] = acc3;
        __syncthreads();

        // gating for cell (bb, uu): gates at gbuf[bb][uu*4 + {0,1,2,3}]
        float4 g4v = *reinterpret_cast<const float4*>(&gbuf[bb * NCOL + uu * 4]);
        float i_ = sigf(g4v.x);
        float f_ = sigf(g4v.y);
        float gg = tanhf_fast(g4v.z);
        float o_ = sigf(g4v.w);
        c_reg = f_ * c_reg + i_ * gg;
        float hnew = o_ * tanhf_fast(c_reg);

        // broadcast h slice to all cluster CTAs (incl. self), into buffer p^1
        uint32_t off = hb_addr +
            (uint32_t)((((p ^ 1) * HID + (int)rank * USLICE + uu) * BG + bb) * 4);
        #pragma unroll
        for (uint32_t r2 = 0; r2 < CLUSTER; r2++) {
            st_shared_cluster_f32(off, r2, hnew);
        }

        cluster_sync_ptx();  // h(t) fully visible cluster-wide; also fences gbuf
    }

    // Final: hT is in buffer 0 (SEQT even). rank-0 CTA computes logits for its
    // 8 batch elements from the full h it holds.
    if (rank == 0 && tid < BG * OUTN) {
        int b = tid >> 1;
        int o = tid & 1;
        float acc = fc_b[o];
        const float* hfin = hb;  // [k][b], buffer 0
        #pragma unroll 8
        for (int k = 0; k < HID; k++) {
            acc = fmaf(hfin[k * BG + b], fc_W[o * HID + k], acc);
        }
        out[(batch_base + b) * OUTN + o] = acc;
    }
}

extern "C" void kernel_launch(void* const* d_in, const int* in_sizes, int n_in,
                              void* d_out, int out_size) {
    (void)in_sizes; (void)n_in; (void)out_size;
    const int*   x     = (const int*)  d_in[0];
    const float* emb   = (const float*)d_in[1];
    const float* W_ih  = (const float*)d_in[2];
    const float* W_hh  = (const float*)d_in[3];
    const float* b_ih  = (const float*)d_in[4];
    const float* b_hh  = (const float*)d_in[5];
    const float* fc_W  = (const float*)d_in[6];
    const float* fc_b  = (const float*)d_in[7];
    float* out = (float*)d_out;

    build_table_kernel<<<VOCABN, 128>>>(emb, W_ih, b_ih, b_hh);

    cudaFuncSetAttribute(lstm_persistent_kernel,
                         cudaFuncAttributeMaxDynamicSharedMemorySize, SMEM_BYTES);
    lstm_persistent_kernel<<<BATCH / BG * CLUSTER, NTHREADS, SMEM_BYTES>>>(
        x, W_hh, fc_W, fc_b, out);
}

// round 2
// speedup vs baseline: 1.9002x; 1.9002x over previous
#include <cuda_runtime.h>
#include <cstdint>

// Problem constants
#define BATCH   128
#define SEQT    2048
#define EMB     128
#define HID     256
#define G4      1024   // 4*HID
#define VOCABN  128
#define OUTN    2

// Decomposition: 16 clusters x 8 CTAs. Cluster owns 8 batch elems.
// CTA owns 32 hidden units (128 gate rows). Thread = (col 0..127, khalf 0..1).
#define CLUSTER   8
#define BG        8
#define USLICE    32
#define NCOL      128
#define NTHREADS  256
#define KHALF     128

// table[v][row] = emb[v] @ W_ih[row]^T + b_ih[row] + b_hh[row]
__device__ float d_table[VOCABN * G4];

__global__ void build_table_kernel(const float* __restrict__ emb,
                                   const float* __restrict__ W_ih,
                                   const float* __restrict__ b_ih,
                                   const float* __restrict__ b_hh) {
    __shared__ float se[EMB];
    int v = blockIdx.x;
    int tid = threadIdx.x;
    if (tid < EMB) se[tid] = emb[v * EMB + tid];
    __syncthreads();
    for (int j = tid; j < G4; j += blockDim.x) {
        float acc = b_ih[j] + b_hh[j];
        const float* w = W_ih + (size_t)j * EMB;
        #pragma unroll 8
        for (int e = 0; e < EMB; e++) acc += se[e] * w[e];
        d_table[v * G4 + j] = acc;
    }
}

// ---------- PTX helpers ----------
__device__ __forceinline__ uint32_t smem_u32(const void* p) {
    uint32_t a;
    asm("{ .reg .u64 t; cvta.to.shared.u64 t, %1; cvt.u32.u64 %0, t; }"
        : "=r"(a) : "l"(p));
    return a;
}
__device__ __forceinline__ void ffma2(unsigned long long& d, unsigned long long a,
                                      unsigned long long b, unsigned long long c) {
    asm("fma.rn.f32x2 %0, %1, %2, %3;" : "=l"(d) : "l"(a), "l"(b), "l"(c));
}
__device__ __forceinline__ unsigned long long pack2(float x, float y) {
    unsigned long long r;
    uint32_t xi = __float_as_uint(x), yi = __float_as_uint(y);
    asm("mov.b64 %0, {%1, %2};" : "=l"(r) : "r"(xi), "r"(yi));
    return r;
}
__device__ __forceinline__ void unpack2(float& x, float& y, unsigned long long v) {
    uint32_t xi, yi;
    asm("mov.b64 {%0, %1}, %2;" : "=r"(xi), "=r"(yi) : "l"(v));
    x = __uint_as_float(xi); y = __uint_as_float(yi);
}
__device__ __forceinline__ void lds_v2_u64(unsigned long long& a, unsigned long long& b,
                                           uint32_t addr) {
    asm volatile("ld.shared.v2.b64 {%0, %1}, [%2];" : "=l"(a), "=l"(b) : "r"(addr));
}
__device__ __forceinline__ void st_cluster_v4(uint32_t addr, uint32_t rank, float4 v) {
    asm volatile(
        "{\n\t.reg .b32 r;\n\t"
        "mapa.shared::cluster.u32 r, %0, %1;\n\t"
        "st.shared::cluster.v4.f32 [r], {%2, %3, %4, %5};\n\t}"
        :: "r"(addr), "r"(rank), "f"(v.x), "f"(v.y), "f"(v.z), "f"(v.w) : "memory");
}
__device__ __forceinline__ void cluster_sync_ptx() {
    asm volatile("barrier.cluster.arrive.aligned;" ::: "memory");
    asm volatile("barrier.cluster.wait.aligned;" ::: "memory");
}
__device__ __forceinline__ float tanh_fast(float x) {
    float y;
    asm("tanh.approx.f32 %0, %1;" : "=f"(y) : "f"(x));
    return y;
}
__device__ __forceinline__ float sig_fast(float x) {
    return fmaf(0.5f, tanh_fast(0.5f * x), 0.5f);
}

// Static SMEM:
//  hb   [2][256][8] : double-buffered hidden state, [buf][k][b]   (16 KB)
//  r0,r1[8][128]    : per-khalf partial preactivations [b][col]   (2x4 KB)
//  stage[256]       : this CTA's h slice in [uu][b] order          (1 KB)
__global__ void __cluster_dims__(CLUSTER, 1, 1) __launch_bounds__(NTHREADS, 1)
lstm_persistent_kernel(const int* __restrict__ x,
                       const float* __restrict__ W_hh,
                       const float* __restrict__ fc_W,
                       const float* __restrict__ fc_b,
                       float* __restrict__ out) {
    __shared__ float hb[2 * HID * BG];
    __shared__ float r0[BG * NCOL];
    __shared__ float r1[BG * NCOL];
    __shared__ float stage[USLICE * BG];

    const int tid = threadIdx.x;
    uint32_t rank;
    asm("mov.u32 %0, %%cluster_ctarank;" : "=r"(rank));
    const int batch_base = (blockIdx.x / CLUSTER) * BG;

    // GEMM role
    const int col = tid & 127;
    const int kh  = tid >> 7;
    const int u_c = col >> 2;
    const int g_c = col & 3;
    const int grow = g_c * HID + (int)rank * USLICE + u_c;

    // Resident weights: w[k] = W_hh[grow][kh*128 + k]
    float w[KHALF];
    {
        const float4* wp = reinterpret_cast<const float4*>(W_hh + (size_t)grow * HID + kh * KHALF);
        #pragma unroll
        for (int i = 0; i < KHALF / 4; i++) {
            float4 v = wp[i];
            w[4 * i + 0] = v.x; w[4 * i + 1] = v.y;
            w[4 * i + 2] = v.z; w[4 * i + 3] = v.w;
        }
    }

    // Zero hidden buffers
    for (int idx = tid; idx < 2 * HID * BG; idx += NTHREADS) hb[idx] = 0.0f;
    __syncthreads();
    cluster_sync_ptx();  // peers must not write into hb while we zero

    // Gating role: thread owns cell (bb, uu)
    const int bb = tid >> 5;
    const int uu = tid & 31;
    float c_reg = 0.0f;

    // Send role: float4 q of own slice to ranks ra and ra+4
    const int q  = tid & 63;
    const int ra = tid >> 6;

    const uint32_t hb_u32 = smem_u32(hb);
    const uint32_t hbase_kh = hb_u32 + (uint32_t)kh * (KHALF * BG * 4);
    float* rme = kh ? r1 : r0;

    // Table gather prefetch (kh==0 warps only; warp-uniform branch)
    const float* tabc = d_table + grow;
    float tnext[BG];
    if (kh == 0) {
        #pragma unroll
        for (int b = 0; b < BG; b++) {
            int v = x[(size_t)(batch_base + b) * SEQT];
            tnext[b] = tabc[(size_t)v * G4];
        }
    }

    #pragma unroll 1
    for (int t = 0; t < SEQT; t++) {
        const int p = t & 1;

        // Init accumulators (kh==0 seeds with gathered xg, kh==1 with zero)
        unsigned long long a0, a1, a2, a3;
        if (kh == 0) {
            a0 = pack2(tnext[0], tnext[1]);
            a1 = pack2(tnext[2], tnext[3]);
            a2 = pack2(tnext[4], tnext[5]);
            a3 = pack2(tnext[6], tnext[7]);
            // prefetch next step's gather (overlaps with GEMM)
            if (t + 1 < SEQT) {
                #pragma unroll
                for (int b = 0; b < BG; b++) {
                    int v = x[(size_t)(batch_base + b) * SEQT + t + 1];
                    tnext[b] = tabc[(size_t)v * G4];
                }
            }
        } else {
            a0 = 0ULL; a1 = 0ULL; a2 = 0ULL; a3 = 0ULL;
        }

        // GEMM: acc[b-pair] += w[k] * h[k][b-pair]; weights in registers
        {
            const uint32_t hbp = hbase_kh + (uint32_t)p * (HID * BG * 4);
            #pragma unroll
            for (int k = 0; k < KHALF; k++) {
                unsigned long long h01, h23, h45, h67;
                lds_v2_u64(h01, h23, hbp + (uint32_t)k * 32u);
                lds_v2_u64(h45, h67, hbp + (uint32_t)k * 32u + 16u);
                uint32_t wi = __float_as_uint(w[k]);
                unsigned long long ww;
                asm("mov.b64 %0, {%1, %1};" : "=l"(ww) : "r"(wi));
                ffma2(a0, ww, h01, a0);
                ffma2(a1, ww, h23, a1);
                ffma2(a2, ww, h45, a2);
                ffma2(a3, ww, h67, a3);
            }
        }

        // Stage partials: rme[b][col]
        {
            float f0, f1, f2, f3, f4, f5, f6, f7;
            unpack2(f0, f1, a0); unpack2(f2, f3, a1);
            unpack2(f4, f5, a2); unpack2(f6, f7, a3);
            rme[0 * NCOL + col] = f0; rme[1 * NCOL + col] = f1;
            rme[2 * NCOL + col] = f2; rme[3 * NCOL + col] = f3;
            rme[4 * NCOL + col] = f4; rme[5 * NCOL + col] = f5;
            rme[6 * NCOL + col] = f6; rme[7 * NCOL + col] = f7;
        }
        __syncthreads();

        // Gating for cell (bb, uu): gates i,f,g,o at cols uu*4 + {0..3}
        {
            float4 ga = *reinterpret_cast<const float4*>(&r0[bb * NCOL + uu * 4]);
            float4 gb = *reinterpret_cast<const float4*>(&r1[bb * NCOL + uu * 4]);
            float i_ = sig_fast(ga.x + gb.x);
            float f_ = sig_fast(ga.y + gb.y);
            float gg = tanh_fast(ga.z + gb.z);
            float o_ = sig_fast(ga.w + gb.w);
            c_reg = fmaf(f_, c_reg, i_ * gg);
            float hnew = o_ * tanh_fast(c_reg);
            stage[uu * BG + bb] = hnew;
        }
        __syncthreads();

        // Broadcast own 1KB slice to all 8 cluster CTAs (vectorized)
        {
            float4 sv = *reinterpret_cast<const float4*>(&stage[q * 4]);
            uint32_t dst = hb_u32 +
                (uint32_t)(((p ^ 1) * HID * BG + (int)rank * USLICE * BG + q * 4) * 4);
            st_cluster_v4(dst, (uint32_t)ra, sv);
            st_cluster_v4(dst, (uint32_t)(ra + 4), sv);
        }

        cluster_sync_ptx();  // release/acquire: h(t) visible cluster-wide
    }

    // Final logits: hT is in buffer 0 ([k][b]); rank-0 CTA has the full h.
    if (rank == 0 && tid < BG * OUTN) {
        int b = tid >> 1;
        int o = tid & 1;
        float acc = fc_b[o];
        #pragma unroll 8
        for (int k = 0; k < HID; k++) {
            acc = fmaf(hb[k * BG + b], fc_W[o * HID + k], acc);
        }
        out[(batch_base + b) * OUTN + o] = acc;
    }
}

extern "C" void kernel_launch(void* const* d_in, const int* in_sizes, int n_in,
                              void* d_out, int out_size) {
    (void)in_sizes; (void)n_in; (void)out_size;
    const int*   x     = (const int*)  d_in[0];
    const float* emb   = (const float*)d_in[1];
    const float* W_ih  = (const float*)d_in[2];
    const float* W_hh  = (const float*)d_in[3];
    const float* b_ih  = (const float*)d_in[4];
    const float* b_hh  = (const float*)d_in[5];
    const float* fc_W  = (const float*)d_in[6];
    const float* fc_b  = (const float*)d_in[7];
    float* out = (float*)d_out;

    build_table_kernel<<<VOCABN, 128>>>(emb, W_ih, b_ih, b_hh);
    lstm_persistent_kernel<<<BATCH / BG * CLUSTER, NTHREADS>>>(
        x, W_hh, fc_W, fc_b, out);
}

// round 3
// speedup vs baseline: 2.1700x; 1.1420x over previous
#include <cuda_runtime.h>
#include <cstdint>

// Problem constants
#define BATCH   128
#define SEQT    2048
#define EMB     128
#define HID     256
#define G4      1024   // 4*HID
#define VOCABN  128
#define OUTN    2

// Decomposition: 16 clusters x 8 CTAs. Cluster owns 8 batch elems.
// CTA owns 32 hidden units (128 gate cols). Thread = (col 0..127, kq 0..3).
#define CLUSTER   8
#define BG        8
#define USLICE    32
#define NCOL      128
#define NTHREADS  512
#define KQN       4
#define KSL       64      // k elements per k-quarter
#define SLICE_BYTES 1024  // USLICE*BG*4
#define STEP_TX     8192  // CLUSTER * SLICE_BYTES

// table[v][row] = emb[v] @ W_ih[row]^T + b_ih[row] + b_hh[row]
__device__ float d_table[VOCABN * G4];

__global__ void build_table_kernel(const float* __restrict__ emb,
                                   const float* __restrict__ W_ih,
                                   const float* __restrict__ b_ih,
                                   const float* __restrict__ b_hh) {
    __shared__ float se[EMB];
    int v = blockIdx.x;
    int tid = threadIdx.x;
    if (tid < EMB) se[tid] = emb[v * EMB + tid];
    __syncthreads();
    for (int j = tid; j < G4; j += blockDim.x) {
        float acc = b_ih[j] + b_hh[j];
        const float* w = W_ih + (size_t)j * EMB;
        #pragma unroll 8
        for (int e = 0; e < EMB; e++) acc += se[e] * w[e];
        d_table[v * G4 + j] = acc;
    }
}

// ---------- PTX helpers ----------
__device__ __forceinline__ uint32_t smem_u32(const void* p) {
    uint32_t a;
    asm("{ .reg .u64 t; cvta.to.shared.u64 t, %1; cvt.u32.u64 %0, t; }"
        : "=r"(a) : "l"(p));
    return a;
}
__device__ __forceinline__ void ffma2(unsigned long long& d, unsigned long long a,
                                      unsigned long long b, unsigned long long c) {
    asm("fma.rn.f32x2 %0, %1, %2, %3;" : "=l"(d) : "l"(a), "l"(b), "l"(c));
}
__device__ __forceinline__ unsigned long long pack2(float x, float y) {
    unsigned long long r;
    uint32_t xi = __float_as_uint(x), yi = __float_as_uint(y);
    asm("mov.b64 %0, {%1, %2};" : "=l"(r) : "r"(xi), "r"(yi));
    return r;
}
__device__ __forceinline__ void unpack2(float& x, float& y, unsigned long long v) {
    uint32_t xi, yi;
    asm("mov.b64 {%0, %1}, %2;" : "=r"(xi), "=r"(yi) : "l"(v));
    x = __uint_as_float(xi); y = __uint_as_float(yi);
}
__device__ __forceinline__ void lds_v2_u64(unsigned long long& a, unsigned long long& b,
                                           uint32_t addr) {
    asm volatile("ld.shared.v2.b64 {%0, %1}, [%2];" : "=l"(a), "=l"(b) : "r"(addr));
}
__device__ __forceinline__ void cluster_sync_ptx() {
    asm volatile("barrier.cluster.arrive.aligned;" ::: "memory");
    asm volatile("barrier.cluster.wait.aligned;" ::: "memory");
}
__device__ __forceinline__ void mbar_init(uint32_t addr, uint32_t cnt) {
    asm volatile("mbarrier.init.shared.b64 [%0], %1;" :: "r"(addr), "r"(cnt) : "memory");
}
__device__ __forceinline__ void mbar_arm(uint32_t addr, uint32_t tx) {
    asm volatile("mbarrier.arrive.expect_tx.shared.b64 _, [%0], %1;"
                 :: "r"(addr), "r"(tx) : "memory");
}
__device__ __forceinline__ void mbar_wait(uint32_t addr, uint32_t parity) {
    uint32_t done;
    asm volatile(
        "{\n\t.reg .pred p;\n\t"
        "mbarrier.try_wait.parity.acquire.cta.shared::cta.b64 p, [%1], %2;\n\t"
        "selp.b32 %0, 1, 0, p;\n\t}"
        : "=r"(done) : "r"(addr), "r"(parity) : "memory");
    if (!done) {
        asm volatile(
            "{\n\t.reg .pred P1;\n\t"
            "WAIT_LOOP_%=:\n\t"
            "mbarrier.try_wait.parity.acquire.cta.shared::cta.b64 P1, [%0], %1, 0x989680;\n\t"
            "@P1 bra.uni WAIT_DONE_%=;\n\t"
            "bra.uni WAIT_LOOP_%=;\n\t"
            "WAIT_DONE_%=:\n\t}"
            :: "r"(addr), "r"(parity) : "memory");
    }
}
// DSMEM bulk copy: local smem -> peer CTA smem, complete_tx on peer's mbarrier.
__device__ __forceinline__ void bulk_s2s_cluster(uint32_t dst_local_off, uint32_t src,
                                                 uint32_t bar_local_off, uint32_t rank,
                                                 uint32_t nbytes) {
    asm volatile(
        "{\n\t.reg .b32 rd, rb;\n\t"
        "mapa.shared::cluster.u32 rd, %0, %3;\n\t"
        "mapa.shared::cluster.u32 rb, %2, %3;\n\t"
        "cp.async.bulk.shared::cluster.shared::cta.mbarrier::complete_tx::bytes "
        "[rd], [%1], %4, [rb];\n\t}"
        :: "r"(dst_local_off), "r"(src), "r"(bar_local_off), "r"(rank), "r"(nbytes)
        : "memory");
}
__device__ __forceinline__ void fence_proxy_async_cta() {
    asm volatile("fence.proxy.async.shared::cta;" ::: "memory");
}
__device__ __forceinline__ float tanh_fast(float x) {
    float y;
    asm("tanh.approx.f32 %0, %1;" : "=f"(y) : "f"(x));
    return y;
}
__device__ __forceinline__ float sig_fast(float x) {
    return fmaf(0.5f, tanh_fast(0.5f * x), 0.5f);
}

// Static SMEM:
//  hb   [2][256][8]  : double-buffered hidden state [buf][k][b]      (16 KB)
//  rp   [4][8][128]  : per-kq partial preactivations [kq][b][col]    (16 KB)
//  stage[2][32][8]   : double-buffered own h-slice in [u][b] order   ( 2 KB)
//  bars [2]          : mbarriers guarding hb buf0/buf1 fills
__global__ void __cluster_dims__(CLUSTER, 1, 1) __launch_bounds__(NTHREADS, 1)
lstm_persistent_kernel(const int* __restrict__ x,
                       const float* __restrict__ W_hh,
                       const float* __restrict__ fc_W,
                       const float* __restrict__ fc_b,
                       float* __restrict__ out) {
    __shared__ float hb[2 * HID * BG];
    __shared__ float rp[KQN][BG * NCOL];
    __shared__ __align__(16) float stage[2][USLICE * BG];
    __shared__ __align__(8) unsigned long long bars[2];

    const int tid = threadIdx.x;
    uint32_t rank;
    asm("mov.u32 %0, %%cluster_ctarank;" : "=r"(rank));
    const int batch_base = (blockIdx.x / CLUSTER) * BG;

    // GEMM role: thread = (col, kq)
    const int col = tid & 127;
    const int kq  = tid >> 7;
    const int u_c = col >> 2;
    const int g_c = col & 3;
    const int grow = g_c * HID + (int)rank * USLICE + u_c;

    // Resident weights: w[k] = W_hh[grow][kq*64 + k]
    float w[KSL];
    {
        const float4* wp = reinterpret_cast<const float4*>(
            W_hh + (size_t)grow * HID + kq * KSL);
        #pragma unroll
        for (int i = 0; i < KSL / 4; i++) {
            float4 v = wp[i];
            w[4 * i + 0] = v.x; w[4 * i + 1] = v.y;
            w[4 * i + 2] = v.z; w[4 * i + 3] = v.w;
        }
    }

    // Zero hidden buffers, init barriers
    for (int idx = tid; idx < 2 * HID * BG; idx += NTHREADS) hb[idx] = 0.0f;
    const uint32_t hb_u32 = smem_u32(hb);
    const uint32_t stage_u32 = smem_u32(stage);
    const uint32_t bars_u32 = smem_u32(bars);
    if (tid == 0) {
        mbar_init(bars_u32 + 0, 1);
        mbar_init(bars_u32 + 8, 1);
    }
    __syncthreads();
    cluster_sync_ptx();   // all CTAs: hb zeroed + bars initialized
    if (tid == 0) mbar_arm(bars_u32 + 8, STEP_TX);  // bar1: fills during step 0

    // Gating role: thread tid<256 owns cell (bb, uu)
    const int bb = tid >> 5;
    const int uu = tid & 31;
    float c_reg = 0.0f;

    int ph0 = 0, ph1 = 0;

    // Table gather prefetch (kq==0 warps only; warp-uniform branch)
    const float* tabc = d_table + grow;
    float tnext[BG];
    if (kq == 0) {
        #pragma unroll
        for (int b = 0; b < BG; b++) {
            int v = x[(size_t)(batch_base + b) * SEQT];
            tnext[b] = tabc[(size_t)v * G4];
        }
    }

    #pragma unroll 1
    for (int t = 0; t < SEQT; t++) {
        const int p = t & 1;

        // Wait for h(t) (buf p) to be fully delivered; t=0 reads local zeros.
        if (t > 0) {
            if (p == 0) { mbar_wait(bars_u32 + 0, ph0); ph0 ^= 1; }
            else        { mbar_wait(bars_u32 + 8, ph1); ph1 ^= 1; }
        }
        // Re-arm bar[p] for its NEXT fill (h(t+2), sent during step t+1).
        // Safe: peers send h(t+2) only after receiving h(t+1), which requires
        // our step-t send, which follows this arm in program order.
        if (tid == 0) mbar_arm(bars_u32 + (uint32_t)p * 8, STEP_TX);

        // Accumulators (kq==0 seeds with gathered xg, others zero)
        unsigned long long a0, a1, a2, a3;
        if (kq == 0) {
            a0 = pack2(tnext[0], tnext[1]);
            a1 = pack2(tnext[2], tnext[3]);
            a2 = pack2(tnext[4], tnext[5]);
            a3 = pack2(tnext[6], tnext[7]);
            if (t + 1 < SEQT) {   // prefetch next step's gather
                #pragma unroll
                for (int b = 0; b < BG; b++) {
                    int v = x[(size_t)(batch_base + b) * SEQT + t + 1];
                    tnext[b] = tabc[(size_t)v * G4];
                }
            }
        } else {
            a0 = 0ULL; a1 = 0ULL; a2 = 0ULL; a3 = 0ULL;
        }

        // GEMM: acc[b-pair] += w[k] * h[kq*64+k][b-pair]
        {
            const uint32_t hbp = hb_u32 + (uint32_t)p * (HID * BG * 4)
                                        + (uint32_t)kq * (KSL * BG * 4);
            #pragma unroll
            for (int k = 0; k < KSL; k++) {
                unsigned long long h01, h23, h45, h67;
                lds_v2_u64(h01, h23, hbp + (uint32_t)k * 32u);
                lds_v2_u64(h45, h67, hbp + (uint32_t)k * 32u + 16u);
                uint32_t wi = __float_as_uint(w[k]);
                unsigned long long ww;
                asm("mov.b64 %0, {%1, %1};" : "=l"(ww) : "r"(wi));
                ffma2(a0, ww, h01, a0);
                ffma2(a1, ww, h23, a1);
                ffma2(a2, ww, h45, a2);
                ffma2(a3, ww, h67, a3);
            }
        }

        // Stage partials: rp[kq][b][col]
        {
            float f0, f1, f2, f3, f4, f5, f6, f7;
            unpack2(f0, f1, a0); unpack2(f2, f3, a1);
            unpack2(f4, f5, a2); unpack2(f6, f7, a3);
            float* rme = rp[kq];
            rme[0 * NCOL + col] = f0; rme[1 * NCOL + col] = f1;
            rme[2 * NCOL + col] = f2; rme[3 * NCOL + col] = f3;
            rme[4 * NCOL + col] = f4; rme[5 * NCOL + col] = f5;
            rme[6 * NCOL + col] = f6; rme[7 * NCOL + col] = f7;
        }
        __syncthreads();

        // Gating for cell (bb, uu): gates i,f,g,o at cols uu*4 + {0..3}
        if (tid < HID) {
            float4 q0 = *reinterpret_cast<const float4*>(&rp[0][bb * NCOL + uu * 4]);
            float4 q1 = *reinterpret_cast<const float4*>(&rp[1][bb * NCOL + uu * 4]);
            float4 q2 = *reinterpret_cast<const float4*>(&rp[2][bb * NCOL + uu * 4]);
            float4 q3 = *reinterpret_cast<const float4*>(&rp[3][bb * NCOL + uu * 4]);
            float i_ = sig_fast(q0.x + q1.x + q2.x + q3.x);
            float f_ = sig_fast(q0.y + q1.y + q2.y + q3.y);
            float gg = tanh_fast(q0.z + q1.z + q2.z + q3.z);
            float o_ = sig_fast(q0.w + q1.w + q2.w + q3.w);
            c_reg = fmaf(f_, c_reg, i_ * gg);
            float hnew = o_ * tanh_fast(c_reg);
            stage[p][uu * BG + bb] = hnew;   // [u][b] = hb slice layout
        }
        __syncthreads();

        // Push own 1KB slice into all 8 cluster CTAs' hb buf p^1 (incl. self),
        // firing complete_tx on each peer's bar[p^1].
        if (tid == 0) {
            fence_proxy_async_cta();  // order generic stage writes vs async read
            uint32_t src = stage_u32 + (uint32_t)p * SLICE_BYTES;
            uint32_t dst_off = hb_u32 + (uint32_t)(p ^ 1) * (HID * BG * 4)
                                      + rank * SLICE_BYTES;
            uint32_t bar_off = bars_u32 + (uint32_t)(p ^ 1) * 8;
            #pragma unroll
            for (uint32_t r2 = 0; r2 < CLUSTER; r2++) {
                bulk_s2s_cluster(dst_off, src, bar_off, r2, SLICE_BYTES);
            }
        }
    }

    // Final h(T) lands in buf 0 (sent during step 2047); wait for it everywhere
    // so no CTA exits while peers' copies into it are in flight.
    mbar_wait(bars_u32 + 0, ph0);

    if (rank == 0 && tid < BG * OUTN) {
        int b = tid >> 1;
        int o = tid & 1;
        float acc = fc_b[o];
        #pragma unroll 8
        for (int k = 0; k < HID; k++) {
            acc = fmaf(hb[k * BG + b], fc_W[o * HID + k], acc);
        }
        out[(batch_base + b) * OUTN + o] = acc;
    }
}

extern "C" void kernel_launch(void* const* d_in, const int* in_sizes, int n_in,
                              void* d_out, int out_size) {
    (void)in_sizes; (void)n_in; (void)out_size;
    const int*   x     = (const int*)  d_in[0];
    const float* emb   = (const float*)d_in[1];
    const float* W_ih  = (const float*)d_in[2];
    const float* W_hh  = (const float*)d_in[3];
    const float* b_ih  = (const float*)d_in[4];
    const float* b_hh  = (const float*)d_in[5];
    const float* fc_W  = (const float*)d_in[6];
    const float* fc_b  = (const float*)d_in[7];
    float* out = (float*)d_out;

    build_table_kernel<<<VOCABN, 128>>>(emb, W_ih, b_ih, b_hh);
    lstm_persistent_kernel<<<BATCH / BG * CLUSTER, NTHREADS>>>(
        x, W_hh, fc_W, fc_b, out);
}

// round 4
// speedup vs baseline: 2.7897x; 1.2856x over previous
#include <cuda_runtime.h>
#include <cstdint>

// Problem constants
#define BATCH   128
#define SEQT    2048
#define EMB     128
#define HID     256
#define G4      1024   // 4*HID
#define VOCABN  128
#define OUTN    2

// Decomposition: 16 clusters x 8 CTAs. Cluster owns 8 batch elems.
// CTA owns 32 hidden units (128 gate cols).
// Thread = (col-pair cp 0..63, k-eighth kq 0..7); owns cols {2cp, 2cp+1}.
#define CLUSTER   8
#define BG        8
#define USLICE    32
#define NCOL      128
#define NTHREADS  512
#define KQN       8
#define KSL       32      // k elements per k-eighth
#define SLICE_BYTES 1024  // USLICE*BG*4
#define STEP_TX     8192  // CLUSTER * SLICE_BYTES

// table[v][row] = emb[v] @ W_ih[row]^T + b_ih[row] + b_hh[row]
__device__ float d_table[VOCABN * G4];

__global__ void build_table_kernel(const float* __restrict__ emb,
                                   const float* __restrict__ W_ih,
                                   const float* __restrict__ b_ih,
                                   const float* __restrict__ b_hh) {
    __shared__ float se[EMB];
    int v = blockIdx.x;
    int tid = threadIdx.x;
    if (tid < EMB) se[tid] = emb[v * EMB + tid];
    __syncthreads();
    for (int j = tid; j < G4; j += blockDim.x) {
        float acc = b_ih[j] + b_hh[j];
        const float* w = W_ih + (size_t)j * EMB;
        #pragma unroll 8
        for (int e = 0; e < EMB; e++) acc += se[e] * w[e];
        d_table[v * G4 + j] = acc;
    }
}

// ---------- PTX helpers ----------
__device__ __forceinline__ uint32_t smem_u32(const void* p) {
    uint32_t a;
    asm("{ .reg .u64 t; cvta.to.shared.u64 t, %1; cvt.u32.u64 %0, t; }"
        : "=r"(a) : "l"(p));
    return a;
}
__device__ __forceinline__ void ffma2(unsigned long long& d, unsigned long long a,
                                      unsigned long long b, unsigned long long c) {
    asm("fma.rn.f32x2 %0, %1, %2, %3;" : "=l"(d) : "l"(a), "l"(b), "l"(c));
}
__device__ __forceinline__ unsigned long long dup2(float x) {
    unsigned long long r;
    uint32_t xi = __float_as_uint(x);
    asm("mov.b64 %0, {%1, %1};" : "=l"(r) : "r"(xi));
    return r;
}
__device__ __forceinline__ void unpack2(float& x, float& y, unsigned long long v) {
    uint32_t xi, yi;
    asm("mov.b64 {%0, %1}, %2;" : "=r"(xi), "=r"(yi) : "l"(v));
    x = __uint_as_float(xi); y = __uint_as_float(yi);
}
__device__ __forceinline__ void lds_v2_u64(unsigned long long& a, unsigned long long& b,
                                           uint32_t addr) {
    asm volatile("ld.shared.v2.b64 {%0, %1}, [%2];" : "=l"(a), "=l"(b) : "r"(addr));
}
__device__ __forceinline__ void cluster_sync_ptx() {
    asm volatile("barrier.cluster.arrive.aligned;" ::: "memory");
    asm volatile("barrier.cluster.wait.aligned;" ::: "memory");
}
__device__ __forceinline__ void mbar_init(uint32_t addr, uint32_t cnt) {
    asm volatile("mbarrier.init.shared.b64 [%0], %1;" :: "r"(addr), "r"(cnt) : "memory");
}
__device__ __forceinline__ void mbar_arm(uint32_t addr, uint32_t tx) {
    asm volatile("mbarrier.arrive.expect_tx.shared.b64 _, [%0], %1;"
                 :: "r"(addr), "r"(tx) : "memory");
}
__device__ __forceinline__ void mbar_wait(uint32_t addr, uint32_t parity) {
    uint32_t done;
    asm volatile(
        "{\n\t.reg .pred p;\n\t"
        "mbarrier.try_wait.parity.acquire.cta.shared::cta.b64 p, [%1], %2;\n\t"
        "selp.b32 %0, 1, 0, p;\n\t}"
        : "=r"(done) : "r"(addr), "r"(parity) : "memory");
    if (!done) {
        asm volatile(
            "{\n\t.reg .pred P1;\n\t"
            "WAIT_LOOP_%=:\n\t"
            "mbarrier.try_wait.parity.acquire.cta.shared::cta.b64 P1, [%0], %1, 0x989680;\n\t"
            "@P1 bra.uni WAIT_DONE_%=;\n\t"
            "bra.uni WAIT_LOOP_%=;\n\t"
            "WAIT_DONE_%=:\n\t}"
            :: "r"(addr), "r"(parity) : "memory");
    }
}
__device__ __forceinline__ void bulk_s2s_cluster(uint32_t dst_local_off, uint32_t src,
                                                 uint32_t bar_local_off, uint32_t rank,
                                                 uint32_t nbytes) {
    asm volatile(
        "{\n\t.reg .b32 rd, rb;\n\t"
        "mapa.shared::cluster.u32 rd, %0, %3;\n\t"
        "mapa.shared::cluster.u32 rb, %2, %3;\n\t"
        "cp.async.bulk.shared::cluster.shared::cta.mbarrier::complete_tx::bytes "
        "[rd], [%1], %4, [rb];\n\t}"
        :: "r"(dst_local_off), "r"(src), "r"(bar_local_off), "r"(rank), "r"(nbytes)
        : "memory");
}
__device__ __forceinline__ void fence_proxy_async_cta() {
    asm volatile("fence.proxy.async.shared::cta;" ::: "memory");
}
__device__ __forceinline__ uint32_t elect_one() {
    uint32_t pred;
    asm volatile(
        "{\n\t.reg .pred p;\n\t"
        "elect.sync _|p, 0xFFFFFFFF;\n\t"
        "selp.b32 %0, 1, 0, p;\n\t}" : "=r"(pred));
    return pred;
}
__device__ __forceinline__ float tanh_fast(float x) {
    float y;
    asm("tanh.approx.f32 %0, %1;" : "=f"(y) : "f"(x));
    return y;
}
__device__ __forceinline__ float sig_fast(float x) {
    return fmaf(0.5f, tanh_fast(0.5f * x), 0.5f);
}

// Static SMEM:
//  hb   [2][256][8]   : double-buffered hidden state [buf][k][b]    (16 KB)
//  rp   [8][8][128]   : per-kq partial preactivations [kq][b][col]  (32 KB)
//  stage[2][32][8]    : double-buffered own h-slice [u][b]          ( 2 KB)
//  bars [2]           : mbarriers guarding hb buf0/buf1 fills
__global__ void __cluster_dims__(CLUSTER, 1, 1) __launch_bounds__(NTHREADS, 1)
lstm_persistent_kernel(const int* __restrict__ x,
                       const float* __restrict__ W_hh,
                       const float* __restrict__ fc_W,
                       const float* __restrict__ fc_b,
                       float* __restrict__ out) {
    __shared__ float hb[2 * HID * BG];
    __shared__ float rp[KQN][BG * NCOL];
    __shared__ __align__(16) float stage[2][USLICE * BG];
    __shared__ __align__(8) unsigned long long bars[2];

    const int tid = threadIdx.x;
    const int wid = tid >> 5;
    uint32_t rank;
    asm("mov.u32 %0, %%cluster_ctarank;" : "=r"(rank));
    const int batch_base = (blockIdx.x / CLUSTER) * BG;

    // GEMM role: thread = (cp, kq); owns cols c0=2cp, c1=2cp+1
    const int cp = tid & 63;
    const int kq = tid >> 6;
    const int c0 = 2 * cp;
    const int c1 = 2 * cp + 1;
    const int grow0 = (c0 & 3) * HID + (int)rank * USLICE + (c0 >> 2);
    const int grow1 = (c1 & 3) * HID + (int)rank * USLICE + (c1 >> 2);

    // Resident weights: w0/w1[k] = W_hh[grow][kq*32 + k]
    float w0[KSL], w1[KSL];
    {
        const float4* wp0 = reinterpret_cast<const float4*>(
            W_hh + (size_t)grow0 * HID + kq * KSL);
        const float4* wp1 = reinterpret_cast<const float4*>(
            W_hh + (size_t)grow1 * HID + kq * KSL);
        #pragma unroll
        for (int i = 0; i < KSL / 4; i++) {
            float4 v0 = wp0[i], v1 = wp1[i];
            w0[4*i+0] = v0.x; w0[4*i+1] = v0.y; w0[4*i+2] = v0.z; w0[4*i+3] = v0.w;
            w1[4*i+0] = v1.x; w1[4*i+1] = v1.y; w1[4*i+2] = v1.z; w1[4*i+3] = v1.w;
        }
    }

    // Zero hidden buffers, init barriers
    for (int idx = tid; idx < 2 * HID * BG; idx += NTHREADS) hb[idx] = 0.0f;
    const uint32_t hb_u32 = smem_u32(hb);
    const uint32_t stage_u32 = smem_u32(stage);
    const uint32_t bars_u32 = smem_u32(bars);
    if (tid == 0) {
        mbar_init(bars_u32 + 0, 1);
        mbar_init(bars_u32 + 8, 1);
    }
    __syncthreads();
    cluster_sync_ptx();   // all CTAs: hb zeroed + bars initialized
    if (tid == 0) mbar_arm(bars_u32 + 8, STEP_TX);  // bar1: fills during step 0

    // Gating role: thread tid<256 owns cell (bb, uu)
    const int bb = tid >> 5;
    const int uu = tid & 31;
    float c_reg = 0.0f;

    // xg gather state (cell threads only)
    const int* xrow = x + (size_t)(batch_base + bb) * SEQT;
    const float* tabu = d_table + (int)rank * USLICE + uu;   // + v*G4 + g*HID
    int vcur = 0;
    if (tid < HID) vcur = xrow[0];

    int ph0 = 0, ph1 = 0;

    #pragma unroll 1
    for (int t = 0; t < SEQT; t++) {
        const int p = t & 1;

        // Prefetch this step's xg (consumed in gating, after GEMM) and next v.
        float xg0, xg1, xg2, xg3;
        if (tid < HID) {
            const float* tv = tabu + (size_t)vcur * G4;
            xg0 = tv[0 * HID];
            xg1 = tv[1 * HID];
            xg2 = tv[2 * HID];
            xg3 = tv[3 * HID];
            if (t + 1 < SEQT) vcur = xrow[t + 1];
        }

        // Wait for h(t) (buf p) delivery; t=0 reads local zeros.
        if (t > 0) {
            if (p == 0) { mbar_wait(bars_u32 + 0, ph0); ph0 ^= 1; }
            else        { mbar_wait(bars_u32 + 8, ph1); ph1 ^= 1; }
        }
        // Re-arm bar[p] for its next fill (h(t+2), sent during step t+1).
        if (tid == 0) mbar_arm(bars_u32 + (uint32_t)p * 8, STEP_TX);

        // GEMM: acc[c][j] += w_c[k] * h[kq*32+k][2j..2j+1]
        unsigned long long a00 = 0, a01 = 0, a02 = 0, a03 = 0;
        unsigned long long a10 = 0, a11 = 0, a12 = 0, a13 = 0;
        {
            const uint32_t hbp = hb_u32 + (uint32_t)p * (HID * BG * 4)
                                        + (uint32_t)kq * (KSL * BG * 4);
            #pragma unroll
            for (int k = 0; k < KSL; k++) {
                unsigned long long h01, h23, h45, h67;
                lds_v2_u64(h01, h23, hbp + (uint32_t)k * 32u);
                lds_v2_u64(h45, h67, hbp + (uint32_t)k * 32u + 16u);
                unsigned long long ww0 = dup2(w0[k]);
                unsigned long long ww1 = dup2(w1[k]);
                ffma2(a00, ww0, h01, a00);
                ffma2(a01, ww0, h23, a01);
                ffma2(a02, ww0, h45, a02);
                ffma2(a03, ww0, h67, a03);
                ffma2(a10, ww1, h01, a10);
                ffma2(a11, ww1, h23, a11);
                ffma2(a12, ww1, h45, a12);
                ffma2(a13, ww1, h67, a13);
            }
        }

        // Stage partials: rp[kq][b][col]
        {
            float* rme = rp[kq];
            float f0, f1;
            unpack2(f0, f1, a00); rme[0*NCOL + c0] = f0; rme[1*NCOL + c0] = f1;
            unpack2(f0, f1, a01); rme[2*NCOL + c0] = f0; rme[3*NCOL + c0] = f1;
            unpack2(f0, f1, a02); rme[4*NCOL + c0] = f0; rme[5*NCOL + c0] = f1;
            unpack2(f0, f1, a03); rme[6*NCOL + c0] = f0; rme[7*NCOL + c0] = f1;
            unpack2(f0, f1, a10); rme[0*NCOL + c1] = f0; rme[1*NCOL + c1] = f1;
            unpack2(f0, f1, a11); rme[2*NCOL + c1] = f0; rme[3*NCOL + c1] = f1;
            unpack2(f0, f1, a12); rme[4*NCOL + c1] = f0; rme[5*NCOL + c1] = f1;
            unpack2(f0, f1, a13); rme[6*NCOL + c1] = f0; rme[7*NCOL + c1] = f1;
        }
        __syncthreads();

        // Gating for cell (bb, uu): gates i,f,g,o at cols uu*4 + {0..3}
        if (tid < HID) {
            float si = xg0, sf = xg1, sg = xg2, so = xg3;
            #pragma unroll
            for (int q = 0; q < KQN; q++) {
                float4 v = *reinterpret_cast<const float4*>(&rp[q][bb * NCOL + uu * 4]);
                si += v.x; sf += v.y; sg += v.z; so += v.w;
            }
            float i_ = sig_fast(si);
            float f_ = sig_fast(sf);
            float gg = tanh_fast(sg);
            float o_ = sig_fast(so);
            c_reg = fmaf(f_, c_reg, i_ * gg);
            float hnew = o_ * tanh_fast(c_reg);
            stage[p][uu * BG + bb] = hnew;   // [u][b] = hb slice layout
        }
        __syncthreads();

        // Push own 1KB slice into all 8 cluster CTAs' hb buf p^1 (incl. self).
        // Warp w (w<8) sends to rank w; one elected lane per warp.
        if (wid < CLUSTER) {
            if (elect_one()) {
                fence_proxy_async_cta();  // order stage writes vs async read
                uint32_t src = stage_u32 + (uint32_t)p * SLICE_BYTES;
                uint32_t dst_off = hb_u32 + (uint32_t)(p ^ 1) * (HID * BG * 4)
                                          + rank * SLICE_BYTES;
                uint32_t bar_off = bars_u32 + (uint32_t)(p ^ 1) * 8;
                bulk_s2s_cluster(dst_off, src, bar_off, (uint32_t)wid, SLICE_BYTES);
            }
        }
    }

    // h(T) lands in buf 0 (sent during step 2047); wait so no CTA exits while
    // peers' copies into its smem are in flight.
    mbar_wait(bars_u32 + 0, ph0);

    if (rank == 0 && tid < BG * OUTN) {
        int b = tid >> 1;
        int o = tid & 1;
        float acc = fc_b[o];
        #pragma unroll 8
        for (int k = 0; k < HID; k++) {
            acc = fmaf(hb[k * BG + b], fc_W[o * HID + k], acc);
        }
        out[(batch_base + b) * OUTN + o] = acc;
    }
}

extern "C" void kernel_launch(void* const* d_in, const int* in_sizes, int n_in,
                              void* d_out, int out_size) {
    (void)in_sizes; (void)n_in; (void)out_size;
    const int*   x     = (const int*)  d_in[0];
    const float* emb   = (const float*)d_in[1];
    const float* W_ih  = (const float*)d_in[2];
    const float* W_hh  = (const float*)d_in[3];
    const float* b_ih  = (const float*)d_in[4];
    const float* b_hh  = (const float*)d_in[5];
    const float* fc_W  = (const float*)d_in[6];
    const float* fc_b  = (const float*)d_in[7];
    float* out = (float*)d_out;

    build_table_kernel<<<VOCABN, 128>>>(emb, W_ih, b_ih, b_hh);
    lstm_persistent_kernel<<<BATCH / BG * CLUSTER, NTHREADS>>>(
        x, W_hh, fc_W, fc_b, out);
}